// round 12
// baseline (speedup 1.0000x reference)
#include <cuda_runtime.h>
#include <cuda_fp16.h>
#include <cstdint>

// SoftmaxRefMatcher: persistent mma.sync fp16 GEMM + fused softmax.
// R12: MUFU-bound fix — ex2.approx.f16x2 (2 exps/op) with per-row online max,
// row sums (s, s·u) computed by a chained tensor-core reduce-MMA (f32 exact).
// BW=8, C=64, N=256, HW=65536, WINDOW=4 -> B=2, NW=6, 12 (w,kh) groups.

#define CK     64
#define NKP    256
#define HW     65536
#define NW     6
#define TPX    128
#define NTILE  512
#define NGRP   12
#define CPG    49
#define NCTA   (NGRP * CPG)     // 588
#define NPART  (CPG * 2)

__device__ __align__(256) __half g_A[NW * NKP * CK];
__device__ __align__(256) __half g_B[2 * HW * CK];
__device__ __align__(256) float4 g_part[NW * NKP * NPART];   // {s,u,v,pad} absolute scale

__device__ __forceinline__ uint32_t smem_u32(const void* p) {
    uint32_t a;
    asm("{ .reg .u64 t; cvta.to.shared.u64 t, %1; cvt.u32.u64 %0, t; }" : "=r"(a) : "l"(p));
    return a;
}
#define LDSM4(R, addr) \
    asm volatile("ldmatrix.sync.aligned.m8n8.x4.shared.b16 {%0,%1,%2,%3}, [%4];" \
        : "=r"((R)[0]), "=r"((R)[1]), "=r"((R)[2]), "=r"((R)[3]) : "r"(addr))
#define MMA16816(D, A, b0, b1) \
    asm volatile("mma.sync.aligned.m16n8k16.row.col.f32.f16.f16.f32 " \
        "{%0,%1,%2,%3}, {%4,%5,%6,%7}, {%8,%9}, {%0,%1,%2,%3};" \
        : "+f"((D)[0]), "+f"((D)[1]), "+f"((D)[2]), "+f"((D)[3]) \
        : "r"((A)[0]), "r"((A)[1]), "r"((A)[2]), "r"((A)[3]), "r"(b0), "r"(b1))
#define CP16(dst, src) \
    asm volatile("cp.async.cg.shared.global [%0], [%1], 16;" :: "r"(dst), "l"(src))
#define CP_COMMIT() asm volatile("cp.async.commit_group;" ::: "memory")
#define CP_WAIT1()  asm volatile("cp.async.wait_group 1;" ::: "memory")
#define BARH(id)    asm volatile("bar.sync %0, 128;" :: "r"(id) : "memory")
// pack two f32 -> f16x2 (first PTX src -> HIGH half)
#define CVTH2(d, hi, lo) \
    asm("cvt.rn.f16x2.f32 %0, %1, %2;" : "=r"(d) : "f"(hi), "f"(lo))
#define EX2H2(x) asm("ex2.approx.f16x2 %0, %0;" : "+r"(x))
#define EX2F(d, a) asm("ex2.approx.ftz.f32 %0, %1;" : "=f"(d) : "f"(a))

// ---------------------------------------------------------------- tgt prep (A: fp16)
__global__ __launch_bounds__(128) void k_prep_tgt(const float* __restrict__ kd) {
    int idx = blockIdx.x;
    int tid = threadIdx.x;
    int w = idx >> 1;
    int n = (idx & 1) * 128 + tid;
    int f = (w / 3) * 4 + (w % 3) + 1;
    const float* src = kd + f * CK * NKP + n;
    float v[CK]; float ss = 0.f;
    #pragma unroll
    for (int c = 0; c < CK; c++) { v[c] = src[c * NKP]; ss += v[c] * v[c]; }
    float inv = 1.f / fmaxf(sqrtf(ss), 1e-12f);
    int base = (w * NKP + n) * CK;
    #pragma unroll
    for (int c = 0; c < CK; c++) g_A[base + c] = __float2half(v[c] * inv);
}

// ---------------------------------------------------------------- src prep (B: fp16, transposed)
__global__ __launch_bounds__(128) void k_prep_src(const float* __restrict__ dd, int blk0) {
    __shared__ uint32_t sH[128 * 33];
    int bid = blockIdx.x + blk0;
    int tid = threadIdx.x;
    int pidx = bid * 128 + tid;
    int b = pidx >> 16;
    const float* src = dd + (size_t)(b * 4) * CK * HW + (pidx & (HW - 1));
    float v[CK]; float ss = 0.f;
    #pragma unroll
    for (int c = 0; c < CK; c++) { v[c] = src[(size_t)c * HW]; ss += v[c] * v[c]; }
    float inv = 1.f / fmaxf(sqrtf(ss), 1e-12f);
    #pragma unroll
    for (int j = 0; j < 32; j++) {
        __half h0 = __float2half(v[2 * j] * inv);
        __half h1 = __float2half(v[2 * j + 1] * inv);
        sH[tid * 33 + j] = (uint32_t)__half_as_ushort(h0) | ((uint32_t)__half_as_ushort(h1) << 16);
    }
    __syncthreads();
    uint32_t* oH = reinterpret_cast<uint32_t*>(g_B) + (size_t)bid * 128 * 32;
    #pragma unroll
    for (int i = 0; i < 32; i++) {
        int u = tid + i * 128;
        int mm = u >> 5, j = u & 31;
        oH[u] = sH[mm * 33 + j];
    }
}

// ---------------------------------------------------------------- persistent GEMM + softmax
#define SM_A 0
#define SM_B(half, buf) (16384 + (half) * 16384 + (buf) * 8192)
#define SM_TOT 49152

__global__ void __launch_bounds__(256, 2) k_gemm() {
    extern __shared__ char smem[];
    uint32_t sb = smem_u32(smem);
    int tid = threadIdx.x;
    int cta = blockIdx.x;
    int grp = cta % NGRP, j = cta / NGRP;
    int w = grp >> 1, kh = grp & 1, b = w / 3;
    int t0 = (j * NTILE) / CPG, t1 = ((j + 1) * NTILE) / CPG;

    int lane = tid & 31, wid = tid >> 5;
    int half = tid >> 7;
    int h = tid & 127;
    int n0 = half * 64;
    int barid = 1 + half;

    // ---- prefetch A (once) ----
    {
        const __half* gA = g_A + (size_t)(w * NKP + kh * 128) * CK;
        #pragma unroll
        for (int i = 0; i < 4; i++) {
            int ch = tid + i * 256;
            int row = ch >> 3, c = ch & 7;
            const __half* src = gA + row * CK + c * 8;
            uint32_t dst = sb + SM_A + row * 128 + (((c ^ (row & 7))) << 4);
            CP16(dst, (const void*)src);
        }
    }
    const __half* gB = g_B + (size_t)b * HW * CK;
    auto prefB = [&](int buf, int t) {
        #pragma unroll
        for (int i = 0; i < 4; i++) {
            int ch = h + i * 128;
            int row = ch >> 3, c = ch & 7;
            const __half* src = gB + (size_t)(t * TPX + n0 + row) * CK + c * 8;
            uint32_t dst = sb + SM_B(half, buf) + row * 128 + (((c ^ (row & 7))) << 4);
            CP16(dst, (const void*)src);
        }
    };
    prefB(0, t0);
    CP_COMMIT();

    // ---- fragment addressing ----
    int m0 = (wid & 3) * 32;
    int aRow = (lane & 7) + ((lane >> 3) & 1) * 8;
    int aCh  = (lane >> 4) & 1;
    int bRow = (lane & 7) + ((lane >> 4) & 1) * 8;
    int bCh  = (lane >> 3) & 1;
    int rA0 = m0 + aRow, rA1 = rA0 + 16;
    uint32_t aB0 = sb + SM_A + rA0 * 128, aB1 = sb + SM_A + rA1 * 128;
    int xA0 = rA0 & 7, xA1 = rA1 & 7;
    uint32_t bOff[4]; int xB[4];
    #pragma unroll
    for (int q = 0; q < 4; q++) {
        int rB = q * 16 + bRow;
        bOff[q] = rB * 128; xB[q] = rB & 7;
    }
    int g = lane >> 2, t4 = lane & 3;
    const float K1 = 144.2695041f;                 // 100 * log2(e)

    // ---- reduce-MMA B fragments: col0 = ones, col1 = u_local (k + 16j) ----
    uint32_t rb0c[4], rb1c[4];
    #pragma unroll
    for (int jj = 0; jj < 4; jj++) {
        float v0 = 0.f, v1 = 0.f, v2 = 0.f, v3 = 0.f;
        if (g == 0) { v0 = v1 = v2 = v3 = 1.f; }
        else if (g == 1) {
            float k0 = (float)(16 * jj + 2 * t4);
            v0 = k0; v1 = k0 + 1.f; v2 = k0 + 8.f; v3 = k0 + 9.f;
        }
        CVTH2(rb0c[jj], v1, v0);
        CVTH2(rb1c[jj], v3, v2);
    }

    // ---- cross-tile online-softmax state (valid in t4==0 lanes) ----
    float Mr[2][2] = {{-9.f, -9.f}, {-9.f, -9.f}};   // running max, acc (cos) domain
    float sA[2][2] = {{0.f,0.f},{0.f,0.f}};
    float uA[2][2] = {{0.f,0.f},{0.f,0.f}};
    float vA[2][2] = {{0.f,0.f},{0.f,0.f}};

    int buf = 0;
    for (int t = t0; t < t1; t++) {
        if (t + 1 < t1) prefB(buf ^ 1, t + 1);
        CP_COMMIT();
        CP_WAIT1();
        if (t == t0) __syncthreads();
        else BARH(barid);

        float acc[2][8][4];
        #pragma unroll
        for (int i = 0; i < 2; i++)
            #pragma unroll
            for (int nt = 0; nt < 8; nt++)
                #pragma unroll
                for (int q = 0; q < 4; q++) acc[i][nt][q] = 0.f;

        uint32_t bB = sb + SM_B(half, buf);
        #pragma unroll
        for (int ks = 0; ks < 4; ks++) {
            uint32_t Af0[4], Af1[4], Bf[4][4];
            int chA = aCh + 2 * ks;
            int chB = bCh + 2 * ks;
            LDSM4(Af0, aB0 + ((chA ^ xA0) << 4));
            LDSM4(Af1, aB1 + ((chA ^ xA1) << 4));
            #pragma unroll
            for (int q = 0; q < 4; q++) LDSM4(Bf[q], bB + bOff[q] + ((chB ^ xB[q]) << 4));
            #pragma unroll
            for (int nt = 0; nt < 8; nt++) {
                uint32_t b0 = Bf[nt >> 1][(nt & 1) * 2];
                uint32_t b1 = Bf[nt >> 1][(nt & 1) * 2 + 1];
                MMA16816(acc[0][nt], Af0, b0, b1);
                MMA16816(acc[1][nt], Af1, b0, b1);
            }
        }

        BARH(barid);       // release buf (epilogue is reg-private)

        // ---- epilogue: per-row max -> f16x2 exp -> reduce-MMA -> online merge ----
        float cu = (float)((t & 1) * 128 + n0);    // global-u offset of this warp tile
        float vt = (float)(t >> 1);
        #pragma unroll
        for (int mt = 0; mt < 2; mt++) {
            float mx0 = fmaxf(acc[mt][0][0], acc[mt][0][1]);
            float mx1 = fmaxf(acc[mt][0][2], acc[mt][0][3]);
            #pragma unroll
            for (int nt = 1; nt < 8; nt++) {
                mx0 = fmaxf(mx0, fmaxf(acc[mt][nt][0], acc[mt][nt][1]));
                mx1 = fmaxf(mx1, fmaxf(acc[mt][nt][2], acc[mt][nt][3]));
            }
            #pragma unroll
            for (int d = 1; d <= 2; d <<= 1) {
                mx0 = fmaxf(mx0, __shfl_xor_sync(0xFFFFFFFFu, mx0, d));
                mx1 = fmaxf(mx1, __shfl_xor_sync(0xFFFFFFFFu, mx1, d));
            }
            float Mo0 = Mr[mt][0], Mo1 = Mr[mt][1];
            float Mn0 = fmaxf(Mo0, mx0), Mn1 = fmaxf(Mo1, mx1);
            Mr[mt][0] = Mn0; Mr[mt][1] = Mn1;
            float csh0 = -K1 * Mn0, csh1 = -K1 * Mn1;
            float r0, r1;
            EX2F(r0, fmaxf(K1 * (Mo0 - Mn0), -126.f));
            EX2F(r1, fmaxf(K1 * (Mo1 - Mn1), -126.f));

            float D[4] = {0.f, 0.f, 0.f, 0.f};     // {s_g, su_g, s_g8, su_g8} in t4==0
            #pragma unroll
            for (int jj = 0; jj < 4; jj++) {
                float t00 = fmaf(acc[mt][2*jj][0],   K1, csh0);
                float t01 = fmaf(acc[mt][2*jj][1],   K1, csh0);
                float t02 = fmaf(acc[mt][2*jj][2],   K1, csh1);
                float t03 = fmaf(acc[mt][2*jj][3],   K1, csh1);
                float t10 = fmaf(acc[mt][2*jj+1][0], K1, csh0);
                float t11 = fmaf(acc[mt][2*jj+1][1], K1, csh0);
                float t12 = fmaf(acc[mt][2*jj+1][2], K1, csh1);
                float t13 = fmaf(acc[mt][2*jj+1][3], K1, csh1);
                uint32_t a0, a1, a2, a3;
                CVTH2(a0, t01, t00); CVTH2(a1, t03, t02);
                CVTH2(a2, t11, t10); CVTH2(a3, t13, t12);
                EX2H2(a0); EX2H2(a1); EX2H2(a2); EX2H2(a3);
                uint32_t Ae[4] = {a0, a1, a2, a3};
                MMA16816(D, Ae, rb0c[jj], rb1c[jj]);
            }
            sA[mt][0] = fmaf(sA[mt][0], r0, D[0]);
            uA[mt][0] = fmaf(uA[mt][0], r0, fmaf(cu, D[0], D[1]));
            vA[mt][0] = fmaf(vA[mt][0], r0, vt * D[0]);
            sA[mt][1] = fmaf(sA[mt][1], r1, D[2]);
            uA[mt][1] = fmaf(uA[mt][1], r1, fmaf(cu, D[2], D[3]));
            vA[mt][1] = fmaf(vA[mt][1], r1, vt * D[2]);
        }
        buf ^= 1;
    }

    // ---- restore absolute scale 2^(K1*(M-1)) and store (t4==0 lanes) ----
    if (t4 == 0) {
        #pragma unroll
        for (int mt = 0; mt < 2; mt++)
            #pragma unroll
            for (int rr = 0; rr < 2; rr++) {
                float sc;
                EX2F(sc, fmaxf(K1 * (Mr[mt][rr] - 1.0f), -126.f));
                int r = m0 + mt * 16 + rr * 8 + g;
                size_t row = (size_t)w * NKP + kh * 128 + r;
                g_part[row * NPART + j * 2 + half] =
                    make_float4(sA[mt][rr] * sc, uA[mt][rr] * sc, vA[mt][rr] * sc, 0.f);
            }
    }
}

// ---------------------------------------------------------------- reduce + tail merged
__global__ __launch_bounds__(256) void k_finish(const float* __restrict__ scores,
                                                float* __restrict__ out) {
    if (blockIdx.x < 192) {
        int row = blockIdx.x * 8 + (threadIdx.x >> 5);
        int lane = threadIdx.x & 31;
        const float4* p = g_part + (size_t)row * NPART;
        float s = 0.f, u = 0.f, v = 0.f;
        #pragma unroll
        for (int i = 0; i < 4; i++) {
            int idx = lane + i * 32;
            if (idx < NPART) {
                float4 q = p[idx];
                s += q.x; u += q.y; v += q.z;
            }
        }
        #pragma unroll
        for (int d = 16; d > 0; d >>= 1) {
            s += __shfl_xor_sync(0xFFFFFFFF, s, d);
            u += __shfl_xor_sync(0xFFFFFFFF, u, d);
            v += __shfl_xor_sync(0xFFFFFFFF, v, d);
        }
        if (lane == 0) {
            float inv = 1.f / s;
            out[row * 2 + 0] = u * inv;
            out[row * 2 + 1] = v * inv;
        }
    } else {
        int w = blockIdx.x - 192, n = threadIdx.x;
        int f = (w / 3) * 4 + (w % 3) + 1;
        out[3072 + w * NKP + n] = scores[f * NKP + n];
        if (n == 0) {
            out[4608 + w] = (float)f;
            out[4614 + w] = (float)((w / 3) * 4);
        }
    }
}

extern "C" void kernel_launch(void* const* d_in, const int* in_sizes, int n_in,
                              void* d_out, int out_size) {
    (void)in_sizes; (void)n_in; (void)out_size;
    const float* scores = (const float*)d_in[0];
    const float* kd     = (const float*)d_in[1];
    const float* dd     = (const float*)d_in[2];
    float* out = (float*)d_out;

    cudaFuncSetAttribute(k_gemm, cudaFuncAttributeMaxDynamicSharedMemorySize, SM_TOT);

    k_prep_tgt<<<NGRP, 128>>>(kd);          // launch 0
    k_prep_src<<<512, 128>>>(dd, 0);        // launch 1
    k_prep_src<<<512, 128>>>(dd, 512);      // launch 2
    k_gemm<<<NCTA, 256, SM_TOT>>>();        // launch 3  (ncu lands here)
    k_finish<<<198, 256>>>(scores, out);    // launch 4
}